// round 3
// baseline (speedup 1.0000x reference)
#include <cuda_runtime.h>

typedef unsigned long long ull;

#define BN 16
#define TILE 128
#define ETH 512

__device__ float g_q[25000 * 224];
__device__ float g_k[25000 * 224];
__device__ float g_v[25000 * 224];

__device__ __forceinline__ float silu_f(float x) { return x / (1.0f + __expf(-x)); }

__device__ __forceinline__ ull fpack2(float lo, float hi) {
    ull u; asm("mov.b64 %0,{%1,%2};" : "=l"(u) : "f"(lo), "f"(hi)); return u;
}
__device__ __forceinline__ void funpack2(ull u, float& lo, float& hi) {
    asm("mov.b64 {%0,%1},%2;" : "=f"(lo), "=f"(hi) : "l"(u));
}
__device__ __forceinline__ void ffma2(ull& d, ull a, ull b) {
    asm("fma.rn.f32x2 %0, %1, %2, %0;" : "+l"(d) : "l"(a), "l"(b));
}

// ---------------------------------------------------------------------------
// Node kernel: q = silu(Wq x), k = silu(Wk x), v = Wv x ; also zeroes outputs
__global__ void __launch_bounds__(256, 1) k_node(
    const float* __restrict__ x,
    const float* __restrict__ Wq, const float* __restrict__ Wk,
    const float* __restrict__ Wv,
    float* __restrict__ outx, float* __restrict__ outev, int N)
{
    extern __shared__ float sm[];
    float* WqT = sm;                // 7168  [h][j*32+i]
    float* WkT = sm + 7168;         // 7168
    float* WvT = sm + 14336;        // 12768 [h][j*57+i]
    float* xs  = sm + 27104;        // BN*224 = 3584

    int tid = threadIdx.x;
    int nb0 = blockIdx.x * BN;
    int cnt = N - nb0; if (cnt > BN) cnt = BN; if (cnt < 0) cnt = 0;

    // zero output rows for this block's nodes
    for (int idx = tid; idx < cnt * 224; idx += 256) {
        int u = idx / 224, f = idx - u * 224;
        outx[(nb0 + u) * 224 + f] = 0.0f;
    }
    for (int idx = tid; idx < cnt * 15; idx += 256) {
        int u = idx / 15, o = idx - u * 15;
        outev[(nb0 + u) * 15 + o] = 0.0f;
    }

    for (int idx = tid; idx < 7168; idx += 256) {
        int h = idx >> 10, r = idx & 1023, i = r >> 5, j = r & 31;
        WqT[h * 1024 + j * 32 + i] = Wq[idx];
        WkT[h * 1024 + j * 32 + i] = Wk[idx];
    }
    for (int idx = tid; idx < 12544; idx += 256) {
        int h = idx / 3136, r = idx - h * 3136, i = r / 56, j = r - i * 56;
        WvT[h * 3192 + j * 57 + i] = Wv[idx];
    }
    for (int idx = tid; idx < BN * 224; idx += 256) {
        int u = idx / 224, f = idx - u * 224;
        xs[idx] = (u < cnt) ? x[(nb0 + u) * 224 + f] : 0.0f;
    }
    __syncthreads();

    if (tid < 224) {
        int h = tid >> 5, iq = tid & 31;
        int hv = tid / 56, iv = tid - hv * 56;
        float aq[BN], ak[BN], av[BN];
#pragma unroll
        for (int u = 0; u < BN; u++) { aq[u] = 0.f; ak[u] = 0.f; av[u] = 0.f; }
#pragma unroll 4
        for (int j = 0; j < 32; j++) {
            float wq = WqT[h * 1024 + j * 32 + iq];
            float wk = WkT[h * 1024 + j * 32 + iq];
#pragma unroll
            for (int u = 0; u < BN; u++) {
                float xv = xs[u * 224 + h * 32 + j];
                aq[u] += wq * xv; ak[u] += wk * xv;
            }
        }
#pragma unroll 4
        for (int j = 0; j < 56; j++) {
            float wv = WvT[hv * 3192 + j * 57 + iv];
#pragma unroll
            for (int u = 0; u < BN; u++) av[u] += wv * xs[u * 224 + hv * 56 + j];
        }
        for (int u = 0; u < cnt; u++) {
            g_q[(nb0 + u) * 224 + tid] = silu_f(aq[u]);
            g_k[(nb0 + u) * 224 + tid] = silu_f(ak[u]);
            g_v[(nb0 + u) * 224 + tid] = av[u];
        }
    }
}

// ---------------------------------------------------------------------------
// smem layout (floats) for k_edge, TILE=128, 512 threads
#define OFF_ACT  0          // 224 * 130 = 29120  (k-major, stride 130)
#define OFF_W2   29120      // 2 * 3584 = 7168 (double buffer)
#define OFF_W1R  36288      // 3584
#define OFF_W1S  39872      // 336
#define OFF_RBF  40208      // 128*32 = 4096
#define OFF_TMP  44304      // 128*15 = 1920
#define OFF_L0   46224      // 128*3 = 384
#define OFF_ALPH 46608      // 128*7 = 896
#define OFF_CUT  47504      // 128
#define OFF_I    47632      // 128
#define OFF_J    47760      // 128
#define EDGE_SMEM_FLOATS 47888

__device__ __forceinline__ void copy_w2_chunk(
    float* dstbuf, const float* __restrict__ W2r, const float* __restrict__ W2s,
    int kc, int tid)
{
    const float* src = (kc < 7) ? (W2r + kc * 16 * 224) : (W2s + (kc - 7) * 16 * 224);
    unsigned db = (unsigned)__cvta_generic_to_shared(dstbuf);
#pragma unroll
    for (int i4 = tid; i4 < 896; i4 += ETH) {
        asm volatile("cp.async.cg.shared.global [%0],[%1],16;"
                     :: "r"(db + i4 * 16), "l"(src + i4 * 4));
    }
    asm volatile("cp.async.commit_group;");
}

__global__ void __launch_bounds__(ETH, 1) k_edge(
    const float* __restrict__ ev, const float* __restrict__ rbf,
    const float* __restrict__ ylm, const float* __restrict__ cut,
    const int* __restrict__ idx_i, const int* __restrict__ idx_j,
    const float* __restrict__ W1r, const float* __restrict__ b1r,
    const float* __restrict__ W2r, const float* __restrict__ b2r,
    const float* __restrict__ W1s, const float* __restrict__ b1s,
    const float* __restrict__ W2s, const float* __restrict__ b2s,
    float* __restrict__ outx, float* __restrict__ outev, int P)
{
    extern __shared__ float sm[];
    int* sI = (int*)(sm + OFF_I);
    int* sJ = (int*)(sm + OFF_J);

    int tid = threadIdx.x, tx = tid & 31, ty = tid >> 5;
    int p0 = blockIdx.x * TILE;
    int vend = P - p0; if (vend > TILE) vend = TILE;

    // preload W2 chunk 0 (hidden under phase A)
    copy_w2_chunk(sm + OFF_W2, W2r, W2s, 0, tid);

    for (int idx = tid; idx < 3584; idx += ETH) sm[OFF_W1R + idx] = W1r[idx];
    for (int idx = tid; idx < 336; idx += ETH) sm[OFF_W1S + idx] = W1s[idx];
    for (int idx = tid; idx < TILE; idx += ETH) {
        int p = p0 + idx; bool v = p < P;
        sI[idx] = v ? idx_i[p] : 0;
        sJ[idx] = v ? idx_j[p] : 0;
        sm[OFF_CUT + idx] = v ? cut[p] : 0.f;
    }
    __syncthreads();
    for (int idx = tid; idx < TILE * 32; idx += ETH) {
        int e = idx >> 5, j = idx & 31; int p = p0 + e;
        sm[OFF_RBF + idx] = (p < P) ? rbf[p * 32 + j] * sm[OFF_CUT + e] : 0.f;
    }
    for (int idx = tid; idx < TILE * 15; idx += ETH) {
        int e = idx / 15, o = idx - e * 15; int p = p0 + e;
        float d = 0.f;
        if (p < P) d = ev[sJ[e] * 15 + o] - ev[sI[e] * 15 + o];
        sm[OFF_TMP + idx] = d * d;
    }
    __syncthreads();
    for (int idx = tid; idx < TILE * 3; idx += ETH) {
        int e = idx / 3, dg = idx - e * 3;
        int o0 = (dg == 0) ? 0 : ((dg == 1) ? 3 : 8);
        int o1 = (dg == 0) ? 3 : ((dg == 1) ? 8 : 15);
        float s = 0.f;
        for (int o = o0; o < o1; o++) s += sm[OFF_TMP + e * 15 + o];
        sm[OFF_L0 + idx] = s;
    }
    __syncthreads();

    // ---- Phase A: hidden acts. threads 0..447: a = t>>1, edge-half = t&1 --
    if (tid < 448) {
        int a = tid >> 1, half = tid & 1;
        int ebase = half * 64;
        bool isr = (a < 112);
        float b0 = isr ? b1r[a] : b1s[a - 112];
        float ws0 = 0, ws1 = 0, ws2 = 0;
        if (!isr) {
            ws0 = sm[OFF_W1S + (a - 112)];
            ws1 = sm[OFF_W1S + 112 + (a - 112)];
            ws2 = sm[OFF_W1S + 224 + (a - 112)];
        }
        for (int ch = 0; ch < 4; ch++) {
            float acc[16];
#pragma unroll
            for (int e = 0; e < 16; e++) acc[e] = b0;
            if (isr) {
#pragma unroll
                for (int j4 = 0; j4 < 8; j4++) {
                    float w0 = sm[OFF_W1R + (j4 * 4 + 0) * 112 + a];
                    float w1 = sm[OFF_W1R + (j4 * 4 + 1) * 112 + a];
                    float w2v = sm[OFF_W1R + (j4 * 4 + 2) * 112 + a];
                    float w3 = sm[OFF_W1R + (j4 * 4 + 3) * 112 + a];
#pragma unroll
                    for (int e = 0; e < 16; e++) {
                        float4 r4 = *(const float4*)&sm[OFF_RBF + (ebase + ch * 16 + e) * 32 + j4 * 4];
                        acc[e] += r4.x * w0 + r4.y * w1 + r4.z * w2v + r4.w * w3;
                    }
                }
            } else {
#pragma unroll
                for (int e = 0; e < 16; e++) {
                    int ee = ebase + ch * 16 + e;
                    acc[e] += sm[OFF_L0 + ee * 3] * ws0 + sm[OFF_L0 + ee * 3 + 1] * ws1
                            + sm[OFF_L0 + ee * 3 + 2] * ws2;
                }
            }
#pragma unroll
            for (int e = 0; e < 16; e++)
                sm[OFF_ACT + a * 130 + ebase + ch * 16 + e] = silu_f(acc[e]);
        }
    }

    // ---- Phase B: w = act @ [W2r;W2s] + b2, f32x2 edge pairs, pipelined ---
    ull acc2[4][7];
#pragma unroll
    for (int r = 0; r < 7; r++) {
        int c = tx + 32 * r;
        float b2 = b2r[c] + b2s[c];
        ull bb = fpack2(b2, b2);
#pragma unroll
        for (int ep = 0; ep < 4; ep++) acc2[ep][r] = bb;
    }

    for (int kc = 0; kc < 14; kc++) {
        if (kc < 13) {
            copy_w2_chunk(sm + OFF_W2 + ((kc + 1) & 1) * 3584, W2r, W2s, kc + 1, tid);
            asm volatile("cp.async.wait_group 1;");
        } else {
            asm volatile("cp.async.wait_group 0;");
        }
        __syncthreads();
        const float* w2b = sm + OFF_W2 + (kc & 1) * 3584;
#pragma unroll 2
        for (int kk = 0; kk < 16; kk++) {
            int k = kc * 16 + kk;
            const ull* ap = (const ull*)&sm[OFF_ACT + k * 130 + ty * 8];
            ull a0 = ap[0], a1 = ap[1], a2 = ap[2], a3 = ap[3];
#pragma unroll
            for (int r = 0; r < 7; r++) {
                float w = w2b[kk * 224 + tx + 32 * r];
                ull ww = fpack2(w, w);
                ffma2(acc2[0][r], a0, ww);
                ffma2(acc2[1][r], a1, ww);
                ffma2(acc2[2][r], a2, ww);
                ffma2(acc2[3][r], a3, ww);
            }
        }
        __syncthreads();
    }

    // ---- Epilogue: alpha[e][r] = cut * sum_c w*q_i*k_j -------------------
#pragma unroll
    for (int ep = 0; ep < 4; ep++) {
        int e0 = ty * 8 + 2 * ep, e1 = e0 + 1;
        int i0 = sI[e0], j0 = sJ[e0], i1 = sI[e1], j1 = sJ[e1];
#pragma unroll
        for (int r = 0; r < 7; r++) {
            int c = tx + 32 * r;
            float wlo, whi; funpack2(acc2[ep][r], wlo, whi);
            float s0 = wlo * g_q[i0 * 224 + c] * g_k[j0 * 224 + c];
            float s1 = whi * g_q[i1 * 224 + c] * g_k[j1 * 224 + c];
#pragma unroll
            for (int off = 16; off; off >>= 1) {
                s0 += __shfl_xor_sync(0xffffffffu, s0, off);
                s1 += __shfl_xor_sync(0xffffffffu, s1, off);
            }
            if (tx == 0) {
                sm[OFF_ALPH + e0 * 7 + r] = s0 * sm[OFF_CUT + e0];
                sm[OFF_ALPH + e1 * 7 + r] = s1 * sm[OFF_CUT + e1];
            }
        }
    }
    __syncthreads();

    // ---- Phase C: segment scatter (idx_i sorted) -------------------------
    if (tid < 224) {
        int h = tid / 56;
        int cur = sI[0]; float acc = 0.f;
#pragma unroll 4
        for (int e = 0; e < vend; e++) {
            int i = sI[e];
            if (i != cur) { atomicAdd(&outx[cur * 224 + tid], acc); acc = 0.f; cur = i; }
            acc += sm[OFF_ALPH + e * 7 + h] * g_v[sJ[e] * 224 + tid];
        }
        atomicAdd(&outx[cur * 224 + tid], acc);
    } else if (tid < 239) {
        int o = tid - 224;
        int dh = (o < 3) ? 4 : ((o < 8) ? 5 : 6);
        int cur = sI[0]; float acc = 0.f;
#pragma unroll 4
        for (int e = 0; e < vend; e++) {
            int i = sI[e];
            if (i != cur) { atomicAdd(&outev[cur * 15 + o], acc); acc = 0.f; cur = i; }
            acc += sm[OFF_ALPH + e * 7 + dh] * ylm[(p0 + e) * 15 + o];
        }
        atomicAdd(&outev[cur * 15 + o], acc);
    }
}

// ---------------------------------------------------------------------------
extern "C" void kernel_launch(void* const* d_in, const int* in_sizes, int n_in,
                              void* d_out, int out_size) {
    const float* x    = (const float*)d_in[0];
    const float* ev   = (const float*)d_in[1];
    const float* rbf  = (const float*)d_in[2];
    const float* ylm  = (const float*)d_in[3];
    const float* cut  = (const float*)d_in[4];
    const int*   idx_i = (const int*)d_in[5];
    const int*   idx_j = (const int*)d_in[6];
    const float* W1r = (const float*)d_in[7];
    const float* b1r = (const float*)d_in[8];
    const float* W2r = (const float*)d_in[9];
    const float* b2r = (const float*)d_in[10];
    const float* W1s = (const float*)d_in[11];
    const float* b1s = (const float*)d_in[12];
    const float* W2s = (const float*)d_in[13];
    const float* b2s = (const float*)d_in[14];
    const float* Wq  = (const float*)d_in[15];
    const float* Wk  = (const float*)d_in[16];
    const float* Wv  = (const float*)d_in[17];

    int N = in_sizes[0] / 224;
    int P = in_sizes[4];
    float* outx  = (float*)d_out;
    float* outev = outx + (size_t)N * 224;

    const int NODE_SMEM = (27104 + BN * 224) * 4;
    const int EDGE_SMEM = EDGE_SMEM_FLOATS * 4;
    cudaFuncSetAttribute(k_node, cudaFuncAttributeMaxDynamicSharedMemorySize, NODE_SMEM);
    cudaFuncSetAttribute(k_edge, cudaFuncAttributeMaxDynamicSharedMemorySize, EDGE_SMEM);

    k_node<<<(N + BN - 1) / BN, 256, NODE_SMEM>>>(x, Wq, Wk, Wv, outx, outev, N);
    k_edge<<<(P + TILE - 1) / TILE, ETH, EDGE_SMEM>>>(
        ev, rbf, ylm, cut, idx_i, idx_j,
        W1r, b1r, W2r, b2r, W1s, b1s, W2s, b2s, outx, outev, P);
}

// round 4
// speedup vs baseline: 1.4433x; 1.4433x over previous
#include <cuda_runtime.h>

typedef unsigned long long ull;

#define BN 16
#define TILE 48
#define NBLK 8334  // ceil(400000/48); computed at launch anyway

__device__ float g_q[25000 * 224];
__device__ float g_k[25000 * 224];
__device__ float g_v[25000 * 224];
__device__ float g_w2p[224 * 256];   // [k][tx*8+r] = W2cat[k][tx+32r], r<7 (r=7 -> 0)
__device__ float g_wqT[7168];        // [h][j*32+i]
__device__ float g_wkT[7168];
__device__ float g_wvT[12544];       // [h][j*56+i]

__device__ __forceinline__ float silu_f(float x) { return x / (1.0f + __expf(-x)); }

__device__ __forceinline__ ull fpack2(float lo, float hi) {
    ull u; asm("mov.b64 %0,{%1,%2};" : "=l"(u) : "f"(lo), "f"(hi)); return u;
}
__device__ __forceinline__ void funpack2(ull u, float& lo, float& hi) {
    asm("mov.b64 {%0,%1},%2;" : "=f"(lo), "=f"(hi) : "l"(u));
}
__device__ __forceinline__ void ffma2(ull& d, ull a, ull b) {
    asm("fma.rn.f32x2 %0, %1, %2, %0;" : "+l"(d) : "l"(a), "l"(b));
}

// ---------------------------------------------------------------------------
// prep: zero outputs, pack W2, transpose node weights
__global__ void k_prep(const float* __restrict__ W2r, const float* __restrict__ W2s,
                       const float* __restrict__ Wq, const float* __restrict__ Wk,
                       const float* __restrict__ Wv,
                       float* __restrict__ outx, float* __restrict__ outev, int N)
{
    int gid = blockIdx.x * blockDim.x + threadIdx.x;
    int st = gridDim.x * blockDim.x;
    int nx = N * 224, nz = N * 239;
    for (int i = gid; i < nz; i += st) {
        if (i < nx) outx[i] = 0.f; else outev[i - nx] = 0.f;
    }
    for (int i = gid; i < 224 * 256; i += st) {
        int k = i >> 8, t8 = i & 255, tx = t8 >> 3, r = t8 & 7;
        float v = 0.f;
        if (r < 7) {
            int c = tx + 32 * r;
            v = (k < 112) ? W2r[k * 224 + c] : W2s[(k - 112) * 224 + c];
        }
        g_w2p[i] = v;
    }
    for (int i = gid; i < 7168; i += st) {
        int h = i >> 10, rem = i & 1023, jj = rem >> 5, ich = rem & 31;
        g_wqT[i] = Wq[h * 1024 + ich * 32 + jj];
        g_wkT[i] = Wk[h * 1024 + ich * 32 + jj];
    }
    for (int i = gid; i < 12544; i += st) {
        int h = i / 3136, rem = i - h * 3136, jj = rem / 56, ich = rem - jj * 56;
        g_wvT[i] = Wv[h * 3136 + ich * 56 + jj];
    }
}

// ---------------------------------------------------------------------------
// node kernel: q = silu(Wq x), k = silu(Wk x), v = Wv x
__global__ void __launch_bounds__(256, 3) k_node(const float* __restrict__ x, int N)
{
    __shared__ float xs[BN * 224];
    int tid = threadIdx.x;
    int nb0 = blockIdx.x * BN;
    int cnt = N - nb0; if (cnt > BN) cnt = BN; if (cnt < 0) cnt = 0;

    for (int idx = tid; idx < BN * 224; idx += 256) {
        int u = idx / 224, f = idx - u * 224;
        xs[idx] = (u < cnt) ? x[(nb0 + u) * 224 + f] : 0.0f;
    }
    __syncthreads();

    if (tid < 224) {
        int h = tid >> 5, iq = tid & 31;
        int hv = tid / 56, iv = tid - hv * 56;
        float aq[BN], ak[BN], av[BN];
#pragma unroll
        for (int u = 0; u < BN; u++) { aq[u] = 0.f; ak[u] = 0.f; av[u] = 0.f; }
#pragma unroll 4
        for (int j = 0; j < 32; j++) {
            float wq = g_wqT[h * 1024 + j * 32 + iq];
            float wk = g_wkT[h * 1024 + j * 32 + iq];
#pragma unroll
            for (int u = 0; u < BN; u++) {
                float xv = xs[u * 224 + h * 32 + j];
                aq[u] += wq * xv; ak[u] += wk * xv;
            }
        }
#pragma unroll 4
        for (int j = 0; j < 56; j++) {
            float wv = g_wvT[hv * 3136 + j * 56 + iv];
#pragma unroll
            for (int u = 0; u < BN; u++) av[u] += wv * xs[u * 224 + hv * 56 + j];
        }
        for (int u = 0; u < cnt; u++) {
            g_q[(nb0 + u) * 224 + tid] = silu_f(aq[u]);
            g_k[(nb0 + u) * 224 + tid] = silu_f(ak[u]);
            g_v[(nb0 + u) * 224 + tid] = av[u];
        }
    }
}

// ---------------------------------------------------------------------------
// edge kernel smem layout (floats)
#define OFF_ACT  0          // 224 * 50 = 11200  (k-major, stride 50, TILE=48 + pad)
#define OFF_RBF  11200      // 48*32 = 1536
#define OFF_TMP  12736      // 48*15 = 720
#define OFF_L0   13456      // 48*3 = 144
#define OFF_ALPH 13600      // 48*7 = 336
#define OFF_CUT  13936      // 48
#define OFF_I    13984      // 48
#define OFF_J    14032      // 48
#define OFF_W2   14084      // 2 * 8*256 = 4096 (double buffer, 16B aligned)
#define EDGE_SMEM_FLOATS 18180

__device__ __forceinline__ void copy_w2_chunk(float* sm, int kc, int tid) {
    // chunk kc = k rows [kc*8, kc*8+8) of g_w2p, 8*256 floats = 512 float4
    unsigned db = (unsigned)__cvta_generic_to_shared(sm + OFF_W2 + (kc & 1) * 2048);
    const float* src = g_w2p + kc * 8 * 256;
#pragma unroll
    for (int q = 0; q < 2; q++) {
        int i4 = tid + q * 256;
        asm volatile("cp.async.cg.shared.global [%0],[%1],16;"
                     :: "r"(db + i4 * 16), "l"(src + i4 * 4));
    }
    asm volatile("cp.async.commit_group;");
}

__global__ void __launch_bounds__(256, 3) k_edge(
    const float* __restrict__ ev, const float* __restrict__ rbf,
    const float* __restrict__ ylm, const float* __restrict__ cut,
    const int* __restrict__ idx_i, const int* __restrict__ idx_j,
    const float* __restrict__ W1r, const float* __restrict__ b1r,
    const float* __restrict__ b2r,
    const float* __restrict__ W1s, const float* __restrict__ b1s,
    const float* __restrict__ b2s,
    float* __restrict__ outx, float* __restrict__ outev, int P)
{
    extern __shared__ float sm[];
    int* sI = (int*)(sm + OFF_I);
    int* sJ = (int*)(sm + OFF_J);

    int tid = threadIdx.x, tx = tid & 31, ty = tid >> 5;
    int p0 = blockIdx.x * TILE;
    int vend = P - p0; if (vend > TILE) vend = TILE;

    copy_w2_chunk(sm, 0, tid);  // preload chunk 0 under phase A

    for (int idx = tid; idx < TILE; idx += 256) {
        int p = p0 + idx; bool v = p < P;
        sI[idx] = v ? idx_i[p] : 0;
        sJ[idx] = v ? idx_j[p] : 0;
        sm[OFF_CUT + idx] = v ? cut[p] : 0.f;
    }
    __syncthreads();
    for (int idx = tid; idx < TILE * 32; idx += 256) {
        int e = idx >> 5, j = idx & 31; int p = p0 + e;
        sm[OFF_RBF + idx] = (p < P) ? rbf[p * 32 + j] * sm[OFF_CUT + e] : 0.f;
    }
    for (int idx = tid; idx < TILE * 15; idx += 256) {
        int e = idx / 15, o = idx - e * 15; int p = p0 + e;
        float d = 0.f;
        if (p < P) d = ev[sJ[e] * 15 + o] - ev[sI[e] * 15 + o];
        sm[OFF_TMP + idx] = d * d;
    }
    __syncthreads();
    for (int idx = tid; idx < TILE * 3; idx += 256) {
        int e = idx / 3, dg = idx - e * 3;
        int o0 = (dg == 0) ? 0 : ((dg == 1) ? 3 : 8);
        int o1 = (dg == 0) ? 3 : ((dg == 1) ? 8 : 15);
        float s = 0.f;
        for (int o = o0; o < o1; o++) s += sm[OFF_TMP + e * 15 + o];
        sm[OFF_L0 + idx] = s;
    }
    __syncthreads();

    // ---- Phase A: hidden acts, thread = channel a (0..223), 3 chunks of 16
    if (tid < 224) {
        int a = tid;
        bool isr = (a < 112);
        float b0 = isr ? b1r[a] : b1s[a - 112];
        float ws0 = 0, ws1 = 0, ws2 = 0;
        if (!isr) {
            ws0 = W1s[a - 112]; ws1 = W1s[112 + a - 112]; ws2 = W1s[224 + a - 112];
        }
        for (int ch = 0; ch < 3; ch++) {
            float acc[16];
#pragma unroll
            for (int e = 0; e < 16; e++) acc[e] = b0;
            if (isr) {
#pragma unroll
                for (int j4 = 0; j4 < 8; j4++) {
                    float w0 = W1r[(j4 * 4 + 0) * 112 + a];
                    float w1 = W1r[(j4 * 4 + 1) * 112 + a];
                    float w2v = W1r[(j4 * 4 + 2) * 112 + a];
                    float w3 = W1r[(j4 * 4 + 3) * 112 + a];
#pragma unroll
                    for (int e = 0; e < 16; e++) {
                        float4 r4 = *(const float4*)&sm[OFF_RBF + (ch * 16 + e) * 32 + j4 * 4];
                        acc[e] += r4.x * w0 + r4.y * w1 + r4.z * w2v + r4.w * w3;
                    }
                }
            } else {
#pragma unroll
                for (int e = 0; e < 16; e++) {
                    int ee = ch * 16 + e;
                    acc[e] += sm[OFF_L0 + ee * 3] * ws0 + sm[OFF_L0 + ee * 3 + 1] * ws1
                            + sm[OFF_L0 + ee * 3 + 2] * ws2;
                }
            }
#pragma unroll
            for (int e = 0; e < 16; e++)
                sm[OFF_ACT + a * 50 + ch * 16 + e] = silu_f(acc[e]);
        }
    }

    // ---- Phase B: w = act @ W2cat + b2, 3 edge-pairs x 7 channels per thread
    ull acc2[3][7];
#pragma unroll
    for (int r = 0; r < 7; r++) {
        int c = tx + 32 * r;
        float b2 = b2r[c] + b2s[c];
        ull bb = fpack2(b2, b2);
#pragma unroll
        for (int ep = 0; ep < 3; ep++) acc2[ep][r] = bb;
    }

    for (int kc = 0; kc < 28; kc++) {
        if (kc < 27) {
            copy_w2_chunk(sm, kc + 1, tid);
            asm volatile("cp.async.wait_group 1;");
        } else {
            asm volatile("cp.async.wait_group 0;");
        }
        __syncthreads();
        const float* wb = sm + OFF_W2 + (kc & 1) * 2048;
#pragma unroll
        for (int kk = 0; kk < 8; kk++) {
            int k = kc * 8 + kk;
            float4 wA = *(const float4*)&wb[kk * 256 + tx * 8];
            float4 wB = *(const float4*)&wb[kk * 256 + tx * 8 + 4];
            const ull* ap = (const ull*)&sm[OFF_ACT + k * 50 + ty * 6];
            ull a0 = ap[0], a1 = ap[1], a2 = ap[2];
            float wv[7] = {wA.x, wA.y, wA.z, wA.w, wB.x, wB.y, wB.z};
#pragma unroll
            for (int r = 0; r < 7; r++) {
                ull ww = fpack2(wv[r], wv[r]);
                ffma2(acc2[0][r], a0, ww);
                ffma2(acc2[1][r], a1, ww);
                ffma2(acc2[2][r], a2, ww);
            }
        }
        __syncthreads();
    }

    // ---- Epilogue: alpha[e][r] = cut * sum_c w*q_i*k_j
#pragma unroll
    for (int ep = 0; ep < 3; ep++) {
        int e0 = ty * 6 + 2 * ep, e1 = e0 + 1;
        int i0 = sI[e0], j0 = sJ[e0], i1 = sI[e1], j1 = sJ[e1];
#pragma unroll
        for (int r = 0; r < 7; r++) {
            int c = tx + 32 * r;
            float wlo, whi; funpack2(acc2[ep][r], wlo, whi);
            float s0 = wlo * g_q[i0 * 224 + c] * g_k[j0 * 224 + c];
            float s1 = whi * g_q[i1 * 224 + c] * g_k[j1 * 224 + c];
#pragma unroll
            for (int off = 16; off; off >>= 1) {
                s0 += __shfl_xor_sync(0xffffffffu, s0, off);
                s1 += __shfl_xor_sync(0xffffffffu, s1, off);
            }
            if (tx == 0) {
                sm[OFF_ALPH + e0 * 7 + r] = s0 * sm[OFF_CUT + e0];
                sm[OFF_ALPH + e1 * 7 + r] = s1 * sm[OFF_CUT + e1];
            }
        }
    }
    __syncthreads();

    // ---- Phase C: segment scatter (idx_i sorted)
    if (tid < 224) {
        int h = tid / 56;
        int cur = sI[0]; float acc = 0.f;
#pragma unroll 4
        for (int e = 0; e < vend; e++) {
            int i = sI[e];
            if (i != cur) { atomicAdd(&outx[cur * 224 + tid], acc); acc = 0.f; cur = i; }
            acc += sm[OFF_ALPH + e * 7 + h] * g_v[sJ[e] * 224 + tid];
        }
        atomicAdd(&outx[cur * 224 + tid], acc);
    } else if (tid < 239) {
        int o = tid - 224;
        int dh = (o < 3) ? 4 : ((o < 8) ? 5 : 6);
        int cur = sI[0]; float acc = 0.f;
#pragma unroll 4
        for (int e = 0; e < vend; e++) {
            int i = sI[e];
            if (i != cur) { atomicAdd(&outev[cur * 15 + o], acc); acc = 0.f; cur = i; }
            acc += sm[OFF_ALPH + e * 7 + dh] * ylm[(p0 + e) * 15 + o];
        }
        atomicAdd(&outev[cur * 15 + o], acc);
    }
}

// ---------------------------------------------------------------------------
extern "C" void kernel_launch(void* const* d_in, const int* in_sizes, int n_in,
                              void* d_out, int out_size) {
    const float* x    = (const float*)d_in[0];
    const float* ev   = (const float*)d_in[1];
    const float* rbf  = (const float*)d_in[2];
    const float* ylm  = (const float*)d_in[3];
    const float* cut  = (const float*)d_in[4];
    const int*   idx_i = (const int*)d_in[5];
    const int*   idx_j = (const int*)d_in[6];
    const float* W1r = (const float*)d_in[7];
    const float* b1r = (const float*)d_in[8];
    const float* W2r = (const float*)d_in[9];
    const float* b2r = (const float*)d_in[10];
    const float* W1s = (const float*)d_in[11];
    const float* b1s = (const float*)d_in[12];
    const float* W2s = (const float*)d_in[13];
    const float* b2s = (const float*)d_in[14];
    const float* Wq  = (const float*)d_in[15];
    const float* Wk  = (const float*)d_in[16];
    const float* Wv  = (const float*)d_in[17];

    int N = in_sizes[0] / 224;
    int P = in_sizes[4];
    float* outx  = (float*)d_out;
    float* outev = outx + (size_t)N * 224;

    const int EDGE_SMEM = EDGE_SMEM_FLOATS * 4;  // 72720 B
    cudaFuncSetAttribute(k_edge, cudaFuncAttributeMaxDynamicSharedMemorySize, EDGE_SMEM);

    k_prep<<<512, 256>>>(W2r, W2s, Wq, Wk, Wv, outx, outev, N);
    k_node<<<(N + BN - 1) / BN, 256>>>(x, N);
    k_edge<<<(P + TILE - 1) / TILE, 256, EDGE_SMEM>>>(
        ev, rbf, ylm, cut, idx_i, idx_j,
        W1r, b1r, b2r, W1s, b1s, b2s, outx, outev, P);
}